// round 7
// baseline (speedup 1.0000x reference)
#include <cuda_runtime.h>
#include <math.h>
#include <stdint.h>

// Problem dims (fixed)
#define NT 2048
#define NB 64
#define NI 256
#define NH 512
#define NG 2048
#define GRID_B 128   // 32 unit-groups x 4 batch-groups, 1 CTA/SM, single wave

// Scratch (__device__ globals; no allocation allowed)
__device__ float g_xw[(size_t)NT * NG * NB];   // [t][col][b]
__device__ float g_h[2 * NH * NB];             // [buf][k][b]
__device__ unsigned g_flag[4 * 32 * 32];       // flag[(bgp*32+slice)*32] = step avail

__device__ __forceinline__ float fast_sigmoid(float x) {
    return __fdividef(1.0f, 1.0f + __expf(-x));
}
__device__ __forceinline__ float fast_tanh(float x) {
    float t = __expf(2.0f * x);
    return 1.0f - __fdividef(2.0f, t + 1.0f);
}

// ---- packed f32x2 helpers ----
__device__ __forceinline__ unsigned long long fma2(unsigned long long a,
                                                   unsigned long long b,
                                                   unsigned long long c) {
    unsigned long long d;
    asm("fma.rn.f32x2 %0, %1, %2, %3;" : "=l"(d) : "l"(a), "l"(b), "l"(c));
    return d;
}
__device__ __forceinline__ unsigned long long pack2(float x, float y) {
    unsigned long long r;
    asm("mov.b64 %0, {%1, %2};" : "=l"(r) : "f"(x), "f"(y));
    return r;
}
__device__ __forceinline__ float2 unpack2(unsigned long long v) {
    float2 f;
    asm("mov.b64 {%0, %1}, %2;" : "=f"(f.x), "=f"(f.y) : "l"(v));
    return f;
}
__device__ __forceinline__ unsigned ld_acquire(const unsigned* p) {
    unsigned v;
    asm volatile("ld.acquire.gpu.global.b32 %0, [%1];" : "=r"(v) : "l"(p));
    return v;
}
__device__ __forceinline__ void cp16(float* smem_dst, const float* gsrc) {
    unsigned d = (unsigned)__cvta_generic_to_shared(smem_dst);
    asm volatile("cp.async.ca.shared.global [%0], [%1], 16;" :: "r"(d), "l"(gsrc));
}

// Prelude: zero h buffer 0 and all flags (every launch/replay).
__global__ void init_kernel() {
    int i = blockIdx.x * blockDim.x + threadIdx.x;
    if (i < NH * NB) g_h[i] = 0.f;
    if (i < 4 * 32 * 32) g_flag[i] = 0u;
}

// ---------------- Phase 1: xW = x @ Wi + B, output TRANSPOSED [t][col][b] ----
// cp.async 3-stage B buffering, register-double-buffered A, 1 sync per k-tile.
__global__ void __launch_bounds__(256, 2)
xw_gemm_kernel(const float* __restrict__ x, const float* __restrict__ Wi,
               const float* __restrict__ bias) {
    __shared__ __align__(16) float As[2][8][132];
    __shared__ __align__(16) float Bs[3][8][128];

    const int tid = threadIdx.x;
    const int tx = tid & 15, ty = tid >> 4;
    const int bm = blockIdx.y << 7, bn = blockIdx.x << 7;
    const int lrow = tid >> 1, lk = (tid & 1) << 2;
    const int brow = tid >> 5, bcol = (tid & 31) << 2;

    unsigned long long acc2[8][4];
    #pragma unroll
    for (int i = 0; i < 8; i++)
        #pragma unroll
        for (int j = 0; j < 4; j++) acc2[i][j] = 0ull;

    const float* xrow = x + (size_t)(bm + lrow) * NI + lk;
    float4 av = *reinterpret_cast<const float4*>(xrow);
    cp16(&Bs[0][brow][bcol], Wi + (size_t)brow * NG + bn + bcol);
    asm volatile("cp.async.commit_group;");

    for (int i = 0; i < 32; i++) {
        const int cur = i & 1;
        As[cur][lk + 0][lrow] = av.x;
        As[cur][lk + 1][lrow] = av.y;
        As[cur][lk + 2][lrow] = av.z;
        As[cur][lk + 3][lrow] = av.w;
        if (i < 31) {
            av = *reinterpret_cast<const float4*>(xrow + (i + 1) * 8);
            cp16(&Bs[(i + 1) % 3][brow][bcol],
                 Wi + (size_t)((i + 1) * 8 + brow) * NG + bn + bcol);
            asm volatile("cp.async.commit_group;");
            asm volatile("cp.async.wait_group 1;");
        } else {
            asm volatile("cp.async.wait_group 0;");
        }
        __syncthreads();

        const float (*Ac)[132] = As[cur];
        const float (*Bc)[128] = Bs[i % 3];
        #pragma unroll
        for (int kk = 0; kk < 8; kk++) {
            float4 t0 = *reinterpret_cast<const float4*>(&Ac[kk][ty << 3]);
            float4 t1 = *reinterpret_cast<const float4*>(&Ac[kk][(ty << 3) + 4]);
            const ulonglong2* brow2 = reinterpret_cast<const ulonglong2*>(&Bc[kk][tx << 3]);
            ulonglong2 bv0 = brow2[0], bv1 = brow2[1];
            unsigned long long b2[4] = {bv0.x, bv0.y, bv1.x, bv1.y};
            float a[8] = {t0.x, t0.y, t0.z, t0.w, t1.x, t1.y, t1.z, t1.w};
            #pragma unroll
            for (int ii = 0; ii < 8; ii++) {
                unsigned long long ap = pack2(a[ii], a[ii]);
                #pragma unroll
                for (int j = 0; j < 4; j++)
                    acc2[ii][j] = fma2(ap, b2[j], acc2[ii][j]);
            }
        }
    }

    float4 bb0 = *reinterpret_cast<const float4*>(bias + bn + (tx << 3));
    float4 bb1 = *reinterpret_cast<const float4*>(bias + bn + (tx << 3) + 4);
    const float bb[8] = {bb0.x, bb0.y, bb0.z, bb0.w, bb1.x, bb1.y, bb1.z, bb1.w};

    const int t_idx = (bm >> 6) + (ty >> 3);
    const int b_base = (ty & 7) << 3;
    float o[8][8];
    #pragma unroll
    for (int i = 0; i < 8; i++)
        #pragma unroll
        for (int p = 0; p < 4; p++) {
            float2 v = unpack2(acc2[i][p]);
            o[i][2 * p] = v.x + bb[2 * p];
            o[i][2 * p + 1] = v.y + bb[2 * p + 1];
        }
    #pragma unroll
    for (int j = 0; j < 8; j++) {
        int col = bn + (tx << 3) + j;
        float* dst = g_xw + ((size_t)t_idx * NG + col) * NB + b_base;
        *reinterpret_cast<float4*>(dst)     = make_float4(o[0][j], o[1][j], o[2][j], o[3][j]);
        *reinterpret_cast<float4*>(dst + 4) = make_float4(o[4][j], o[5][j], o[6][j], o[7][j]);
    }
}

// ---------------- Phase 2: persistent recurrence, warp-specialized ----------------
// CTA (ug, bgp): units 16ug..+15 (all 4 gates = 64 cols), batches 16bgp..+15.
// Warps 0-7 (matmul): warp w owns k rows [64w, 64w+64): waits 4 slice flags +
//   own flag, stages DUPLICATED h into shD[k][32] (ready FFMA2 pairs, zero movs),
//   computes partials, stores sRed[w][g][b16][u16].
// Warps 8-15 (cell): prefetch xW, sync, direct 32-LDS reduce + cell, h store,
//   named bar, flag publish, out stores off critical path.
// SMEM: sWh [512][64] perm 128KB | shD [512][32] 64KB | sRed [8][4][16][16] 32KB.
#define SMEM2_FLOATS (NH * 64 + NH * 32 + 8 * 1024)

__global__ void __launch_bounds__(512, 1)
lstm_rec_kernel(const float* __restrict__ Wh, float* __restrict__ out, int write_state) {
    extern __shared__ float smem[];
    float* sWh  = smem;                 // [k][64] permuted: wA chunks | wB chunks
    float* shD  = sWh + NH * 64;        // [k][32] duplicated h
    float* sRed = shD + NH * 32;        // [8][4][16][16]

    const int tid = threadIdx.x;
    const int wid = tid >> 5;
    const int lane = tid & 31;
    const int ug = blockIdx.x >> 2;
    const int bgp = blockIdx.x & 3;

    // Wh fill, permuted row: phys = half*32 + cg*4 + i4 <-> logical col cg*8+half*4+i4.
    for (int idx = tid; idx < NH * 64; idx += 512) {
        int k = idx >> 6, ph = idx & 63;
        int half = ph >> 5, rem = ph & 31, cg = rem >> 2, i4 = rem & 3;
        int c = cg * 8 + half * 4 + i4;
        int gcol = ((c >> 4) << 9) + (ug << 4) + (c & 15);
        sWh[idx] = Wh[(size_t)k * NG + gcol];
    }
    __syncthreads();

    if (wid < 8) {
        // ---- matmul role ----
        const int cg = lane >> 2, bq = lane & 3;
        const int g_of = cg >> 1, u8 = (cg & 1) << 3;
        const int rl = lane >> 2, part = lane & 3;
        const unsigned* fl[4];
        #pragma unroll
        for (int s = 0; s < 4; s++)
            fl[s] = &g_flag[(bgp * 32 + (wid * 4 + s)) * 32];
        const unsigned* flown = &g_flag[(bgp * 32 + ug) * 32];

        const float* wptr0 = sWh + (wid << 6) * 64 + (cg << 2);
        const float* hptr0 = shD + (wid << 6) * 32 + (bq << 3);

        for (int t = 0; t < NT; t++) {
            // Wait: 4 staging slices + own CTA's publish (sRed reuse safety).
            #pragma unroll
            for (int s = 0; s < 4; s++)
                while (ld_acquire(fl[s]) < (unsigned)t) { __nanosleep(20); }
            while (ld_acquire(flown) < (unsigned)t) { __nanosleep(20); }

            // Stage own 64 rows, duplicated: shD[k][2b] = shD[k][2b+1] = h[k][b].
            {
                const float* src = g_h + (t & 1) * (NH * NB) + (bgp << 4) + (part << 2);
                #pragma unroll
                for (int i = 0; i < 8; i++) {
                    int row = (wid << 6) + (i << 3) + rl;
                    float4 v = __ldcg(reinterpret_cast<const float4*>(src + row * NB));
                    float* d = shD + row * 32 + (part << 3);
                    *reinterpret_cast<float4*>(d)     = make_float4(v.x, v.x, v.y, v.y);
                    *reinterpret_cast<float4*>(d + 4) = make_float4(v.z, v.z, v.w, v.w);
                }
            }
            __syncwarp();

            // Matmul over 64 k rows: 4 col-pairs x 4 batches, pure FFMA2.
            unsigned long long acc[4][4];
            #pragma unroll
            for (int cp = 0; cp < 4; cp++)
                #pragma unroll
                for (int j = 0; j < 4; j++) acc[cp][j] = 0ull;

            const float* wp_ = wptr0;
            const float* hp_ = hptr0;
            #pragma unroll 8
            for (int kl = 0; kl < 64; kl++) {
                ulonglong2 wA = *reinterpret_cast<const ulonglong2*>(wp_);
                ulonglong2 wB = *reinterpret_cast<const ulonglong2*>(wp_ + 32);
                ulonglong2 hA = *reinterpret_cast<const ulonglong2*>(hp_);
                ulonglong2 hB = *reinterpret_cast<const ulonglong2*>(hp_ + 4);
                unsigned long long wq[4] = {wA.x, wA.y, wB.x, wB.y};
                unsigned long long hd[4] = {hA.x, hA.y, hB.x, hB.y};
                #pragma unroll
                for (int cp = 0; cp < 4; cp++) {
                    acc[cp][0] = fma2(wq[cp], hd[0], acc[cp][0]);
                    acc[cp][1] = fma2(wq[cp], hd[1], acc[cp][1]);
                    acc[cp][2] = fma2(wq[cp], hd[2], acc[cp][2]);
                    acc[cp][3] = fma2(wq[cp], hd[3], acc[cp][3]);
                }
                wp_ += 64;
                hp_ += 32;
            }

            // Partials: sRed[w][g][b16][u16].
            #pragma unroll
            for (int j = 0; j < 4; j++) {
                float2 p0 = unpack2(acc[0][j]);
                float2 p1 = unpack2(acc[1][j]);
                float2 p2 = unpack2(acc[2][j]);
                float2 p3 = unpack2(acc[3][j]);
                float* dst = sRed + (wid << 10) + (g_of << 8) + (((bq << 2) + j) << 4) + u8;
                *reinterpret_cast<float4*>(dst)     = make_float4(p0.x, p0.y, p1.x, p1.y);
                *reinterpret_cast<float4*>(dst + 4) = make_float4(p2.x, p2.y, p3.x, p3.y);
            }
            __syncthreads();   // rendezvous with cell warps (1 per step)
        }
    } else {
        // ---- cell role ----
        const int ct = tid - 256;
        const int u_ = ct & 15, b2 = ct >> 4;
        const int hrow = (ug << 4) + u_;
        const int bglob = (bgp << 4) + b2;
        const unsigned* myflag = &g_flag[(bgp * 32 + ug) * 32];
        float c_reg = 0.f;

        for (int t = 0; t < NT; t++) {
            const float* xwt = g_xw + (size_t)t * ((size_t)NG * NB) + (size_t)hrow * NB + bglob;
            float xw0 = __ldg(xwt);
            float xw1 = __ldg(xwt + (size_t)(1 << 9) * NB);
            float xw2 = __ldg(xwt + (size_t)(2 << 9) * NB);
            float xw3 = __ldg(xwt + (size_t)(3 << 9) * NB);

            __syncthreads();   // partials of step t ready

            float G0 = xw0, G1 = xw1, G2 = xw2, G3 = xw3;
            const float* rp0 = sRed + (b2 << 4) + u_;
            #pragma unroll
            for (int w = 0; w < 8; w++) {
                const float* rp = rp0 + (w << 10);
                G0 += rp[0];
                G1 += rp[256];
                G2 += rp[512];
                G3 += rp[768];
            }
            float ig = fast_sigmoid(G0);
            float fg = fast_sigmoid(G1);
            float gg = fast_tanh(G2);
            float og = fast_sigmoid(G3);
            c_reg = fg * c_reg + ig * gg;
            float h = og * fast_tanh(c_reg);

            __stcg(&g_h[((t + 1) & 1) * (NH * NB) + hrow * NB + bglob], h);
            asm volatile("bar.sync 9, 256;");   // all 256 cell threads stored h
            if (tid == 256) {
                __threadfence();
                asm volatile("st.release.gpu.global.b32 [%0], %1;"
                             :: "l"(myflag), "r"((unsigned)(t + 1)) : "memory");
            }
            // Off the critical path:
            out[((size_t)t * NB + bglob) * NH + hrow] = h;
            if (write_state && t == NT - 1) {
                size_t base = (size_t)NT * NB * NH;
                out[base + (size_t)bglob * NH + hrow] = h;
                out[base + (size_t)NB * NH + (size_t)bglob * NH + hrow] = c_reg;
            }
        }
    }
}

extern "C" void kernel_launch(void* const* d_in, const int* in_sizes, int n_in,
                              void* d_out, int out_size) {
    const float* x  = (const float*)d_in[0];
    const float* Wi = (const float*)d_in[1];
    const float* Wh = (const float*)d_in[2];
    const float* B  = (const float*)d_in[3];
    float* out = (float*)d_out;

    const int smem_bytes = SMEM2_FLOATS * (int)sizeof(float);   // 229376 B
    cudaFuncSetAttribute(lstm_rec_kernel, cudaFuncAttributeMaxDynamicSharedMemorySize, smem_bytes);

    init_kernel<<<32, 1024>>>();   // zero h0 + flags (every launch/replay)

    dim3 gA(NG / 128, (NT * NB) / 128);
    xw_gemm_kernel<<<gA, 256>>>(x, Wi, B);

    const long long need_full = (long long)NT * NB * NH + 2LL * NB * NH;
    int write_state = ((long long)out_size >= need_full) ? 1 : 0;

    lstm_rec_kernel<<<GRID_B, 512, smem_bytes>>>(Wh, out, write_state);
}